// round 7
// baseline (speedup 1.0000x reference)
#include <cuda_runtime.h>
#include <cuda_bf16.h>
#include <mma.h>
#include <cstdint>

using namespace nvcuda;

#define N_NODES   20000
#define N_EDGES   160000
#define N_GRAPHS  64
#define IN_DIM    128
#define HID       512
#define N_CLASSES 16
#define MROWS     20096   // 157 * 128, padded so GEMM needs no row guards

// ---------------- scratch (static device globals; no allocation) ----------------
__device__ float g_bufA[MROWS * HID];   // GEMM output (gather source)
__device__ float g_bufB[MROWS * HID];   // layer-3 fp32 activations (pool input)
__device__ float g_dout[N_NODES];       // rsqrt(out-degree)
__device__ float g_din [N_NODES];       // rsqrt(in-degree)
__device__ float g_pool[N_GRAPHS * HID];
__device__ float g_cnt [N_GRAPHS];
__device__ float g_mlp1[N_GRAPHS * HID];
__device__ float g_mlp2[N_GRAPHS * HID];
// CSR (by dst)
__device__ int g_cin   [N_NODES];
__device__ int g_cout  [N_NODES];
__device__ int g_rowoff[N_NODES + 1];
__device__ int g_cursor[N_NODES];
__device__ int g_csrc  [N_EDGES];
// bf16 split buffers (A rows padded to MROWS)
__device__ __nv_bfloat16 g_Ahi[MROWS * HID];
__device__ __nv_bfloat16 g_Alo[MROWS * HID];
__device__ __nv_bfloat16 g_Whi[HID * HID];   // transposed: [n][k]
__device__ __nv_bfloat16 g_Wlo[HID * HID];

// ---------------- utility kernels ----------------
__global__ void zero_i2(int* a, int* b, int n) {
    int i = blockIdx.x * blockDim.x + threadIdx.x;
    if (i < n) { a[i] = 0; b[i] = 0; }
}
__global__ void zero_f(float* p, int n) {
    int i = blockIdx.x * blockDim.x + threadIdx.x;
    if (i < n) p[i] = 0.0f;
}
__global__ void deg_kernel(const int* __restrict__ src, const int* __restrict__ dst,
                           int* cout_, int* cin_) {
    int e = blockIdx.x * blockDim.x + threadIdx.x;
    if (e < N_EDGES) {
        atomicAdd(&cout_[src[e]], 1);
        atomicAdd(&cin_ [dst[e]], 1);
    }
}

// Single-block exclusive scan over cin -> rowoff/cursor; also din/dout rsqrt.
__global__ __launch_bounds__(1024) void scan_kernel(
    const int* __restrict__ cin_, const int* __restrict__ cout_,
    int* __restrict__ rowoff, int* __restrict__ cursor,
    float* __restrict__ din, float* __restrict__ dout)
{
    __shared__ int tmp[1024];
    __shared__ int running;
    int tid = threadIdx.x;
    if (tid == 0) running = 0;
    __syncthreads();
    for (int c0 = 0; c0 < N_NODES; c0 += 1024) {
        int idx = c0 + tid;
        int v = (idx < N_NODES) ? cin_[idx] : 0;
        tmp[tid] = v;
        __syncthreads();
        #pragma unroll
        for (int off = 1; off < 1024; off <<= 1) {
            int t = (tid >= off) ? tmp[tid - off] : 0;
            __syncthreads();
            tmp[tid] += t;
            __syncthreads();
        }
        int excl = running + tmp[tid] - v;
        if (idx < N_NODES) {
            rowoff[idx] = excl;
            cursor[idx] = excl;
            din [idx] = rsqrtf(fmaxf((float)cin_ [idx], 1.0f));
            dout[idx] = rsqrtf(fmaxf((float)cout_[idx], 1.0f));
        }
        __syncthreads();
        if (tid == 1023) running += tmp[1023];
        __syncthreads();
    }
    if (tid == 0) rowoff[N_NODES] = running;
}

__global__ void bin_kernel(const int* __restrict__ src, const int* __restrict__ dst,
                           int* __restrict__ cursor, int* __restrict__ csrc) {
    int e = blockIdx.x * blockDim.x + threadIdx.x;
    if (e < N_EDGES) {
        int pos = atomicAdd(&cursor[dst[e]], 1);
        csrc[pos] = src[e];
    }
}

// Split fp32 activation (scaled by rowScale) into bf16 hi + lo  (layer-1 input)
__global__ void split_scaled(const float* __restrict__ in, const float* __restrict__ scale,
                             __nv_bfloat16* __restrict__ hi, __nv_bfloat16* __restrict__ lo,
                             int total4, int K) {
    int i = blockIdx.x * blockDim.x + threadIdx.x;
    if (i >= total4) return;
    int row = (i * 4) / K;
    float s = scale[row];
    float4 v = reinterpret_cast<const float4*>(in)[i];
    v.x *= s; v.y *= s; v.z *= s; v.w *= s;
    __nv_bfloat16 h0 = __float2bfloat16(v.x);
    __nv_bfloat16 h1 = __float2bfloat16(v.y);
    __nv_bfloat16 h2 = __float2bfloat16(v.z);
    __nv_bfloat16 h3 = __float2bfloat16(v.w);
    __nv_bfloat16 l0 = __float2bfloat16(v.x - __bfloat162float(h0));
    __nv_bfloat16 l1 = __float2bfloat16(v.y - __bfloat162float(h1));
    __nv_bfloat16 l2 = __float2bfloat16(v.z - __bfloat162float(h2));
    __nv_bfloat16 l3 = __float2bfloat16(v.w - __bfloat162float(h3));
    __nv_bfloat162* hp = reinterpret_cast<__nv_bfloat162*>(hi) + i * 2;
    __nv_bfloat162* lp = reinterpret_cast<__nv_bfloat162*>(lo) + i * 2;
    hp[0] = __nv_bfloat162(h0, h1); hp[1] = __nv_bfloat162(h2, h3);
    lp[0] = __nv_bfloat162(l0, l1); lp[1] = __nv_bfloat162(l2, l3);
}

// Transpose + split weights: W[k][n] fp32 -> Wt_hi/lo[n][k] bf16
__global__ void wsplit(const float* __restrict__ W,
                       __nv_bfloat16* __restrict__ hi, __nv_bfloat16* __restrict__ lo,
                       int K, int N) {
    int idx = blockIdx.x * blockDim.x + threadIdx.x;
    if (idx >= K * N) return;
    int k = idx / N, n = idx % N;
    float v = W[idx];
    __nv_bfloat16 h = __float2bfloat16(v);
    hi[n * K + k] = h;
    lo[n * K + k] = __float2bfloat16(v - __bfloat162float(h));
}

// ========== fused CSR gather + finalize (+ split) ==========
__global__ __launch_bounds__(128) void gather_fin(
    const float* __restrict__ feat, const int* __restrict__ csrc,
    const int* __restrict__ rowoff,
    const float* __restrict__ din, const float* __restrict__ dout,
    const float* __restrict__ b,
    __nv_bfloat16* __restrict__ hi, __nv_bfloat16* __restrict__ lo,
    float* __restrict__ f32out, int mode)
{
    __shared__ int sidx[256];
    const int n   = blockIdx.x;
    const int tid = threadIdx.x;
    const int beg = rowoff[n];
    const int end = rowoff[n + 1];
    const int deg = end - beg;
    const int nl  = min(deg, 256);
    for (int i = tid; i < nl; i += 128) sidx[i] = csrc[beg + i];
    __syncthreads();

    const int c = tid * 4;
    float4 acc = make_float4(0.f, 0.f, 0.f, 0.f);
    int i = 0;
    for (; i + 4 <= nl; i += 4) {
        const float4 v0 = *reinterpret_cast<const float4*>(feat + (size_t)sidx[i]     * HID + c);
        const float4 v1 = *reinterpret_cast<const float4*>(feat + (size_t)sidx[i + 1] * HID + c);
        const float4 v2 = *reinterpret_cast<const float4*>(feat + (size_t)sidx[i + 2] * HID + c);
        const float4 v3 = *reinterpret_cast<const float4*>(feat + (size_t)sidx[i + 3] * HID + c);
        acc.x += v0.x + v1.x + v2.x + v3.x;
        acc.y += v0.y + v1.y + v2.y + v3.y;
        acc.z += v0.z + v1.z + v2.z + v3.z;
        acc.w += v0.w + v1.w + v2.w + v3.w;
    }
    for (; i < nl; i++) {
        const float4 v = *reinterpret_cast<const float4*>(feat + (size_t)sidx[i] * HID + c);
        acc.x += v.x; acc.y += v.y; acc.z += v.z; acc.w += v.w;
    }
    for (int e = beg + 256; e < end; e++) {
        int s = csrc[e];
        const float4 v = *reinterpret_cast<const float4*>(feat + (size_t)s * HID + c);
        acc.x += v.x; acc.y += v.y; acc.z += v.z; acc.w += v.w;
    }

    const float s = din[n];
    const float4 bb = *reinterpret_cast<const float4*>(b + c);
    acc.x = fmaxf(fmaf(acc.x, s, bb.x), 0.f);
    acc.y = fmaxf(fmaf(acc.y, s, bb.y), 0.f);
    acc.z = fmaxf(fmaf(acc.z, s, bb.z), 0.f);
    acc.w = fmaxf(fmaf(acc.w, s, bb.w), 0.f);

    if (mode == 0) {
        const float so = dout[n];
        acc.x *= so; acc.y *= so; acc.z *= so; acc.w *= so;
        __nv_bfloat16 h0 = __float2bfloat16(acc.x);
        __nv_bfloat16 h1 = __float2bfloat16(acc.y);
        __nv_bfloat16 h2 = __float2bfloat16(acc.z);
        __nv_bfloat16 h3 = __float2bfloat16(acc.w);
        __nv_bfloat16 l0 = __float2bfloat16(acc.x - __bfloat162float(h0));
        __nv_bfloat16 l1 = __float2bfloat16(acc.y - __bfloat162float(h1));
        __nv_bfloat16 l2 = __float2bfloat16(acc.z - __bfloat162float(h2));
        __nv_bfloat16 l3 = __float2bfloat16(acc.w - __bfloat162float(h3));
        size_t o = (size_t)n * HID + c;
        *reinterpret_cast<__nv_bfloat162*>(hi + o)     = __nv_bfloat162(h0, h1);
        *reinterpret_cast<__nv_bfloat162*>(hi + o + 2) = __nv_bfloat162(h2, h3);
        *reinterpret_cast<__nv_bfloat162*>(lo + o)     = __nv_bfloat162(l0, l1);
        *reinterpret_cast<__nv_bfloat162*>(lo + o + 2) = __nv_bfloat162(l2, l3);
    } else {
        *reinterpret_cast<float4*>(f32out + (size_t)n * HID + c) = acc;
    }
}

// ================= WMMA bf16-split GEMM, cp.async 3-stage pipeline =================
#define GBM 128
#define GBN 256
#define GBK 32
#define LDS_T 40                      // 32 + 8 pad bf16 elems (80B stride)
#define STAGE_ROWS 768                // Ahi 128 + Alo 128 + Bhi 256 + Blo 256
#define STAGE_ELEMS (STAGE_ROWS * LDS_T)
#define NSTAGES 3

__device__ __forceinline__ void cp16(__nv_bfloat16* smem_dst, const __nv_bfloat16* gsrc) {
    uint32_t s = (uint32_t)__cvta_generic_to_shared(smem_dst);
    asm volatile("cp.async.cg.shared.global [%0], [%1], 16;" :: "r"(s), "l"(gsrc));
}

__device__ __forceinline__ void load_stage(
    const __nv_bfloat16* __restrict__ Ahi, const __nv_bfloat16* __restrict__ Alo,
    const __nv_bfloat16* __restrict__ Bhi, const __nv_bfloat16* __restrict__ Blo,
    __nv_bfloat16* stage, int m0, int n0, int k0, int K, int tid)
{
    #pragma unroll
    for (int i = 0; i < 12; i++) {
        int o   = tid + i * 256;
        int row = o >> 2;
        int q   = o & 3;
        const __nv_bfloat16* g;
        if      (row < 128) g = Ahi + (size_t)(m0 + row)       * K + k0;
        else if (row < 256) g = Alo + (size_t)(m0 + row - 128) * K + k0;
        else if (row < 512) g = Bhi + (size_t)(n0 + row - 256) * K + k0;
        else                g = Blo + (size_t)(n0 + row - 512) * K + k0;
        cp16(stage + row * LDS_T + q * 8, g + q * 8);
    }
}

__global__ __launch_bounds__(256, 1) void gemm_wmma(
    const __nv_bfloat16* __restrict__ Ahi, const __nv_bfloat16* __restrict__ Alo,
    const __nv_bfloat16* __restrict__ Bhi, const __nv_bfloat16* __restrict__ Blo,
    float* __restrict__ C, int K)
{
    extern __shared__ __nv_bfloat16 sm[];
    const int tid = threadIdx.x;
    const int wid = tid >> 5;
    const int warp_m = wid >> 2;
    const int warp_n = wid & 3;
    const int m0 = blockIdx.x * GBM;
    const int n0 = blockIdx.y * GBN;

    wmma::fragment<wmma::accumulator, 16, 16, 16, float> c[4][4];
    #pragma unroll
    for (int i = 0; i < 4; i++)
        #pragma unroll
        for (int j = 0; j < 4; j++) wmma::fill_fragment(c[i][j], 0.0f);

    const int nchunks = K / GBK;   // >= 4 always (K=128 or 512)

    load_stage(Ahi, Alo, Bhi, Blo, sm, m0, n0, 0, K, tid);
    asm volatile("cp.async.commit_group;");
    load_stage(Ahi, Alo, Bhi, Blo, sm + STAGE_ELEMS, m0, n0, GBK, K, tid);
    asm volatile("cp.async.commit_group;");

    for (int ch = 0; ch < nchunks; ch++) {
        if (ch + 2 < nchunks) {
            load_stage(Ahi, Alo, Bhi, Blo, sm + ((ch + 2) % NSTAGES) * STAGE_ELEMS,
                       m0, n0, (ch + 2) * GBK, K, tid);
            asm volatile("cp.async.commit_group;");
            asm volatile("cp.async.wait_group 2;");
        } else if (ch + 1 < nchunks) {
            asm volatile("cp.async.wait_group 1;");
        } else {
            asm volatile("cp.async.wait_group 0;");
        }
        __syncthreads();

        __nv_bfloat16* st = sm + (ch % NSTAGES) * STAGE_ELEMS;
        __nv_bfloat16* sAhi = st;
        __nv_bfloat16* sAlo = st + 128 * LDS_T;
        __nv_bfloat16* sBhi = st + 256 * LDS_T;
        __nv_bfloat16* sBlo = st + 512 * LDS_T;

        #pragma unroll
        for (int ks = 0; ks < GBK; ks += 16) {
            // hoist ALL fragments for this ks-step, then pass-major MMA sweeps
            wmma::fragment<wmma::matrix_b, 16, 16, 16, __nv_bfloat16, wmma::col_major> bh[4], bl[4];
            wmma::fragment<wmma::matrix_a, 16, 16, 16, __nv_bfloat16, wmma::row_major> ah[4], al[4];
            #pragma unroll
            for (int j = 0; j < 4; j++) {
                int nn = warp_n * 64 + j * 16;
                wmma::load_matrix_sync(bh[j], sBhi + nn * LDS_T + ks, LDS_T);
                wmma::load_matrix_sync(bl[j], sBlo + nn * LDS_T + ks, LDS_T);
            }
            #pragma unroll
            for (int i = 0; i < 4; i++) {
                int mm = warp_m * 64 + i * 16;
                wmma::load_matrix_sync(ah[i], sAhi + mm * LDS_T + ks, LDS_T);
                wmma::load_matrix_sync(al[i], sAlo + mm * LDS_T + ks, LDS_T);
            }
            // pass 1: ah x bh — 16 independent accumulators
            #pragma unroll
            for (int i = 0; i < 4; i++)
                #pragma unroll
                for (int j = 0; j < 4; j++)
                    wmma::mma_sync(c[i][j], ah[i], bh[j], c[i][j]);
            // pass 2: ah x bl
            #pragma unroll
            for (int i = 0; i < 4; i++)
                #pragma unroll
                for (int j = 0; j < 4; j++)
                    wmma::mma_sync(c[i][j], ah[i], bl[j], c[i][j]);
            // pass 3: al x bh
            #pragma unroll
            for (int i = 0; i < 4; i++)
                #pragma unroll
                for (int j = 0; j < 4; j++)
                    wmma::mma_sync(c[i][j], al[i], bh[j], c[i][j]);
        }
        __syncthreads();
    }

    #pragma unroll
    for (int i = 0; i < 4; i++) {
        int row = m0 + warp_m * 64 + i * 16;
        #pragma unroll
        for (int j = 0; j < 4; j++) {
            int col = n0 + warp_n * 64 + j * 16;
            wmma::store_matrix_sync(C + (size_t)row * HID + col, c[i][j], HID,
                                    wmma::mem_row_major);
        }
    }
}

// ---------------- pooling ----------------
__global__ void count_kernel(const int* __restrict__ gid, float* __restrict__ cnt) {
    __shared__ int s[N_GRAPHS];
    if (threadIdx.x < N_GRAPHS) s[threadIdx.x] = 0;
    __syncthreads();
    for (int i = threadIdx.x; i < N_NODES; i += blockDim.x)
        atomicAdd(&s[gid[i]], 1);
    __syncthreads();
    if (threadIdx.x < N_GRAPHS) cnt[threadIdx.x] = (float)s[threadIdx.x];
}

#define POOL_CHUNK 160
__global__ void pool_kernel(const float* __restrict__ h, const int* __restrict__ gid,
                            float* __restrict__ pool) {
    __shared__ int sg[POOL_CHUNK];
    int n0 = blockIdx.x * POOL_CHUNK;
    int n1 = min(n0 + POOL_CHUNK, N_NODES);
    for (int i = threadIdx.x; i < n1 - n0; i += blockDim.x) sg[i] = gid[n0 + i];
    __syncthreads();

    int c = threadIdx.x * 4;
    float4 acc = make_float4(0.f, 0.f, 0.f, 0.f);
    int cur = sg[0];
    for (int n = n0; n < n1; n++) {
        int g = sg[n - n0];
        if (g != cur) {
            float* p = pool + cur * HID + c;
            atomicAdd(p + 0, acc.x); atomicAdd(p + 1, acc.y);
            atomicAdd(p + 2, acc.z); atomicAdd(p + 3, acc.w);
            acc = make_float4(0.f, 0.f, 0.f, 0.f);
            cur = g;
        }
        float4 v = *reinterpret_cast<const float4*>(h + n * HID + c);
        acc.x += v.x; acc.y += v.y; acc.z += v.z; acc.w += v.w;
    }
    float* p = pool + cur * HID + c;
    atomicAdd(p + 0, acc.x); atomicAdd(p + 1, acc.y);
    atomicAdd(p + 2, acc.z); atomicAdd(p + 3, acc.w);
}

__global__ void div_kernel(float* __restrict__ pool, const float* __restrict__ cnt) {
    int i = blockIdx.x * blockDim.x + threadIdx.x;
    if (i < N_GRAPHS * HID) {
        float inv = 1.0f / fmaxf(cnt[i / HID], 1.0f);
        pool[i] *= inv;
    }
}

// ---------------- MLP head ----------------
__global__ void dense512(const float* __restrict__ in, const float* __restrict__ W,
                         const float* __restrict__ b, float* __restrict__ out) {
    __shared__ float sh[HID];
    int g = blockIdx.x;
    for (int i = threadIdx.x; i < HID; i += blockDim.x) sh[i] = in[g * HID + i];
    __syncthreads();
    int n = blockIdx.y * 256 + threadIdx.x;
    float acc = b[n];
    #pragma unroll 8
    for (int k = 0; k < HID; k++)
        acc = fmaf(sh[k], W[k * HID + n], acc);
    out[g * HID + n] = fmaxf(acc, 0.0f);
}

__global__ void dense_out(const float* __restrict__ in, const float* __restrict__ W,
                          const float* __restrict__ b, float* __restrict__ out) {
    int g = blockIdx.x;
    int n = threadIdx.x;
    float acc = b[n];
    for (int k = 0; k < HID; k++)
        acc = fmaf(in[g * HID + k], W[k * N_CLASSES + n], acc);
    out[g * N_CLASSES + n] = acc;
}

// ---------------- launch ----------------
extern "C" void kernel_launch(void* const* d_in, const int* in_sizes, int n_in,
                              void* d_out, int out_size) {
    const float* x    = (const float*)d_in[0];
    const int*   src  = (const int*)  d_in[1];
    const int*   dst  = (const int*)  d_in[2];
    const int*   gid  = (const int*)  d_in[3];
    const float* W1   = (const float*)d_in[4];
    const float* b1   = (const float*)d_in[5];
    const float* W2   = (const float*)d_in[6];
    const float* b2   = (const float*)d_in[7];
    const float* W3   = (const float*)d_in[8];
    const float* b3   = (const float*)d_in[9];
    const float* Wc1  = (const float*)d_in[10];
    const float* bc1  = (const float*)d_in[11];
    const float* Wc2  = (const float*)d_in[12];
    const float* bc2  = (const float*)d_in[13];
    const float* Wc3  = (const float*)d_in[14];
    const float* bc3  = (const float*)d_in[15];
    float* out = (float*)d_out;

    float *bufA, *bufB, *doutv, *dinv, *pool, *cnt, *m1, *m2;
    int *cin_, *cout_, *rowoff, *cursor, *csrc;
    __nv_bfloat16 *Ahi, *Alo, *Whi, *Wlo;
    cudaGetSymbolAddress((void**)&bufA,   g_bufA);
    cudaGetSymbolAddress((void**)&bufB,   g_bufB);
    cudaGetSymbolAddress((void**)&doutv,  g_dout);
    cudaGetSymbolAddress((void**)&dinv,   g_din);
    cudaGetSymbolAddress((void**)&pool,   g_pool);
    cudaGetSymbolAddress((void**)&cnt,    g_cnt);
    cudaGetSymbolAddress((void**)&m1,     g_mlp1);
    cudaGetSymbolAddress((void**)&m2,     g_mlp2);
    cudaGetSymbolAddress((void**)&cin_,   g_cin);
    cudaGetSymbolAddress((void**)&cout_,  g_cout);
    cudaGetSymbolAddress((void**)&rowoff, g_rowoff);
    cudaGetSymbolAddress((void**)&cursor, g_cursor);
    cudaGetSymbolAddress((void**)&csrc,   g_csrc);
    cudaGetSymbolAddress((void**)&Ahi,    g_Ahi);
    cudaGetSymbolAddress((void**)&Alo,    g_Alo);
    cudaGetSymbolAddress((void**)&Whi,    g_Whi);
    cudaGetSymbolAddress((void**)&Wlo,    g_Wlo);

    const int smem_gemm = NSTAGES * STAGE_ELEMS * (int)sizeof(__nv_bfloat16);  // 184320
    cudaFuncSetAttribute(gemm_wmma, cudaFuncAttributeMaxDynamicSharedMemorySize, smem_gemm);

    const int nb_nodes = (N_NODES + 255) / 256;
    const int nb_edges = (N_EDGES + 255) / 256;
    dim3 gemm_grid(MROWS / GBM, HID / GBN);   // (157, 2)

    // ---- CSR build + degree normalizers ----
    zero_i2<<<nb_nodes, 256>>>(cin_, cout_, N_NODES);
    deg_kernel<<<nb_edges, 256>>>(src, dst, cout_, cin_);
    scan_kernel<<<1, 1024>>>(cin_, cout_, rowoff, cursor, dinv, doutv);
    bin_kernel<<<nb_edges, 256>>>(src, dst, cursor, csrc);

    // ---- layer 1 ----
    {
        wsplit<<<(IN_DIM * HID + 255) / 256, 256>>>(W1, Whi, Wlo, IN_DIM, HID);
        int t4 = N_NODES * IN_DIM / 4;
        split_scaled<<<(t4 + 255) / 256, 256>>>(x, doutv, Ahi, Alo, t4, IN_DIM);
        gemm_wmma<<<gemm_grid, 256, smem_gemm>>>(Ahi, Alo, Whi, Wlo, bufA, IN_DIM);
        gather_fin<<<N_NODES, 128>>>(bufA, csrc, rowoff, dinv, doutv, b1,
                                     Ahi, Alo, nullptr, 0);
    }
    // ---- layer 2 ----
    {
        wsplit<<<(HID * HID + 255) / 256, 256>>>(W2, Whi, Wlo, HID, HID);
        gemm_wmma<<<gemm_grid, 256, smem_gemm>>>(Ahi, Alo, Whi, Wlo, bufA, HID);
        gather_fin<<<N_NODES, 128>>>(bufA, csrc, rowoff, dinv, doutv, b2,
                                     Ahi, Alo, nullptr, 0);
    }
    // ---- layer 3 ----
    {
        wsplit<<<(HID * HID + 255) / 256, 256>>>(W3, Whi, Wlo, HID, HID);
        gemm_wmma<<<gemm_grid, 256, smem_gemm>>>(Ahi, Alo, Whi, Wlo, bufA, HID);
        gather_fin<<<N_NODES, 128>>>(bufA, csrc, rowoff, dinv, doutv, b3,
                                     nullptr, nullptr, bufB, 1);
    }

    // ---- mean pooling ----
    zero_f<<<(N_GRAPHS * HID + 255) / 256, 256>>>(pool, N_GRAPHS * HID);
    count_kernel<<<1, 256>>>(gid, cnt);
    pool_kernel<<<(N_NODES + POOL_CHUNK - 1) / POOL_CHUNK, 128>>>(bufB, gid, pool);
    div_kernel<<<(N_GRAPHS * HID + 255) / 256, 256>>>(pool, cnt);

    // ---- MLP head ----
    dense512<<<dim3(N_GRAPHS, 2), 256>>>(pool, Wc1, bc1, m1);
    dense512<<<dim3(N_GRAPHS, 2), 256>>>(m1, Wc2, bc2, m2);
    dense_out<<<N_GRAPHS, 16>>>(m2, Wc3, bc3, out);
}

// round 8
// speedup vs baseline: 1.2343x; 1.2343x over previous
#include <cuda_runtime.h>
#include <cuda_fp16.h>
#include <mma.h>
#include <cstdint>

using namespace nvcuda;

#define N_NODES   20000
#define N_EDGES   160000
#define N_GRAPHS  64
#define IN_DIM    128
#define HID       512
#define N_CLASSES 16
#define MROWS     20096   // 157 * 128, padded so GEMM needs no row guards

// ---------------- scratch (static device globals; no allocation) ----------------
__device__ float g_bufA[MROWS * HID];   // GEMM output (gather source)
__device__ float g_bufB[MROWS * HID];   // layer-3 fp32 activations (pool input)
__device__ float g_dout[N_NODES];       // rsqrt(out-degree)
__device__ float g_din [N_NODES];       // rsqrt(in-degree)
__device__ float g_pool[N_GRAPHS * HID];
__device__ float g_cnt [N_GRAPHS];
__device__ float g_mlp1[N_GRAPHS * HID];
__device__ float g_mlp2[N_GRAPHS * HID];
// CSR (by dst)
__device__ int g_cin   [N_NODES];
__device__ int g_cout  [N_NODES];
__device__ int g_rowoff[N_NODES + 1];
__device__ int g_cursor[N_NODES];
__device__ int g_csrc  [N_EDGES];
// fp16 buffers (A rows padded to MROWS)
__device__ __half g_Ahi[MROWS * HID];
__device__ __half g_Alo[MROWS * HID];
__device__ __half g_Wt [HID * HID];   // transposed: [n][k], single fp16

// ---------------- utility kernels ----------------
__global__ void zero_i2(int* a, int* b, int n) {
    int i = blockIdx.x * blockDim.x + threadIdx.x;
    if (i < n) { a[i] = 0; b[i] = 0; }
}
__global__ void zero_f(float* p, int n) {
    int i = blockIdx.x * blockDim.x + threadIdx.x;
    if (i < n) p[i] = 0.0f;
}
__global__ void deg_kernel(const int* __restrict__ src, const int* __restrict__ dst,
                           int* cout_, int* cin_) {
    int e = blockIdx.x * blockDim.x + threadIdx.x;
    if (e < N_EDGES) {
        atomicAdd(&cout_[src[e]], 1);
        atomicAdd(&cin_ [dst[e]], 1);
    }
}

// Single-block exclusive scan over cin -> rowoff/cursor; also din/dout rsqrt.
__global__ __launch_bounds__(1024) void scan_kernel(
    const int* __restrict__ cin_, const int* __restrict__ cout_,
    int* __restrict__ rowoff, int* __restrict__ cursor,
    float* __restrict__ din, float* __restrict__ dout)
{
    __shared__ int tmp[1024];
    __shared__ int running;
    int tid = threadIdx.x;
    if (tid == 0) running = 0;
    __syncthreads();
    for (int c0 = 0; c0 < N_NODES; c0 += 1024) {
        int idx = c0 + tid;
        int v = (idx < N_NODES) ? cin_[idx] : 0;
        tmp[tid] = v;
        __syncthreads();
        #pragma unroll
        for (int off = 1; off < 1024; off <<= 1) {
            int t = (tid >= off) ? tmp[tid - off] : 0;
            __syncthreads();
            tmp[tid] += t;
            __syncthreads();
        }
        int excl = running + tmp[tid] - v;
        if (idx < N_NODES) {
            rowoff[idx] = excl;
            cursor[idx] = excl;
            din [idx] = rsqrtf(fmaxf((float)cin_ [idx], 1.0f));
            dout[idx] = rsqrtf(fmaxf((float)cout_[idx], 1.0f));
        }
        __syncthreads();
        if (tid == 1023) running += tmp[1023];
        __syncthreads();
    }
    if (tid == 0) rowoff[N_NODES] = running;
}

__global__ void bin_kernel(const int* __restrict__ src, const int* __restrict__ dst,
                           int* __restrict__ cursor, int* __restrict__ csrc) {
    int e = blockIdx.x * blockDim.x + threadIdx.x;
    if (e < N_EDGES) {
        int pos = atomicAdd(&cursor[dst[e]], 1);
        csrc[pos] = src[e];
    }
}

// Split fp32 activation (scaled by rowScale) into fp16 hi + lo  (layer-1 input)
__global__ void split_scaled(const float* __restrict__ in, const float* __restrict__ scale,
                             __half* __restrict__ hi, __half* __restrict__ lo,
                             int total4, int K) {
    int i = blockIdx.x * blockDim.x + threadIdx.x;
    if (i >= total4) return;
    int row = (i * 4) / K;
    float s = scale[row];
    float4 v = reinterpret_cast<const float4*>(in)[i];
    v.x *= s; v.y *= s; v.z *= s; v.w *= s;
    __half h0 = __float2half(v.x);
    __half h1 = __float2half(v.y);
    __half h2 = __float2half(v.z);
    __half h3 = __float2half(v.w);
    __half l0 = __float2half(v.x - __half2float(h0));
    __half l1 = __float2half(v.y - __half2float(h1));
    __half l2 = __float2half(v.z - __half2float(h2));
    __half l3 = __float2half(v.w - __half2float(h3));
    __half2* hp = reinterpret_cast<__half2*>(hi) + i * 2;
    __half2* lp = reinterpret_cast<__half2*>(lo) + i * 2;
    hp[0] = __half2(h0, h1); hp[1] = __half2(h2, h3);
    lp[0] = __half2(l0, l1); lp[1] = __half2(l2, l3);
}

// Transpose weights: W[k][n] fp32 -> Wt[n][k] fp16
__global__ void wsplit(const float* __restrict__ W, __half* __restrict__ t,
                       int K, int N) {
    int idx = blockIdx.x * blockDim.x + threadIdx.x;
    if (idx >= K * N) return;
    int k = idx / N, n = idx % N;
    t[n * K + k] = __float2half(W[idx]);
}

// ========== fused CSR gather + finalize (+ split) ==========
__global__ __launch_bounds__(128) void gather_fin(
    const float* __restrict__ feat, const int* __restrict__ csrc,
    const int* __restrict__ rowoff,
    const float* __restrict__ din, const float* __restrict__ dout,
    const float* __restrict__ b,
    __half* __restrict__ hi, __half* __restrict__ lo,
    float* __restrict__ f32out, int mode)
{
    __shared__ int sidx[256];
    const int n   = blockIdx.x;
    const int tid = threadIdx.x;
    const int beg = rowoff[n];
    const int end = rowoff[n + 1];
    const int deg = end - beg;
    const int nl  = min(deg, 256);
    for (int i = tid; i < nl; i += 128) sidx[i] = csrc[beg + i];
    __syncthreads();

    const int c = tid * 4;
    float4 acc = make_float4(0.f, 0.f, 0.f, 0.f);
    int i = 0;
    for (; i + 4 <= nl; i += 4) {
        const float4 v0 = *reinterpret_cast<const float4*>(feat + (size_t)sidx[i]     * HID + c);
        const float4 v1 = *reinterpret_cast<const float4*>(feat + (size_t)sidx[i + 1] * HID + c);
        const float4 v2 = *reinterpret_cast<const float4*>(feat + (size_t)sidx[i + 2] * HID + c);
        const float4 v3 = *reinterpret_cast<const float4*>(feat + (size_t)sidx[i + 3] * HID + c);
        acc.x += v0.x + v1.x + v2.x + v3.x;
        acc.y += v0.y + v1.y + v2.y + v3.y;
        acc.z += v0.z + v1.z + v2.z + v3.z;
        acc.w += v0.w + v1.w + v2.w + v3.w;
    }
    for (; i < nl; i++) {
        const float4 v = *reinterpret_cast<const float4*>(feat + (size_t)sidx[i] * HID + c);
        acc.x += v.x; acc.y += v.y; acc.z += v.z; acc.w += v.w;
    }
    for (int e = beg + 256; e < end; e++) {
        int s = csrc[e];
        const float4 v = *reinterpret_cast<const float4*>(feat + (size_t)s * HID + c);
        acc.x += v.x; acc.y += v.y; acc.z += v.z; acc.w += v.w;
    }

    const float s = din[n];
    const float4 bb = *reinterpret_cast<const float4*>(b + c);
    acc.x = fmaxf(fmaf(acc.x, s, bb.x), 0.f);
    acc.y = fmaxf(fmaf(acc.y, s, bb.y), 0.f);
    acc.z = fmaxf(fmaf(acc.z, s, bb.z), 0.f);
    acc.w = fmaxf(fmaf(acc.w, s, bb.w), 0.f);

    if (mode == 0) {
        const float so = dout[n];
        acc.x *= so; acc.y *= so; acc.z *= so; acc.w *= so;
        __half h0 = __float2half(acc.x);
        __half h1 = __float2half(acc.y);
        __half h2 = __float2half(acc.z);
        __half h3 = __float2half(acc.w);
        __half l0 = __float2half(acc.x - __half2float(h0));
        __half l1 = __float2half(acc.y - __half2float(h1));
        __half l2 = __float2half(acc.z - __half2float(h2));
        __half l3 = __float2half(acc.w - __half2float(h3));
        size_t o = (size_t)n * HID + c;
        *reinterpret_cast<__half2*>(hi + o)     = __half2(h0, h1);
        *reinterpret_cast<__half2*>(hi + o + 2) = __half2(h2, h3);
        *reinterpret_cast<__half2*>(lo + o)     = __half2(l0, l1);
        *reinterpret_cast<__half2*>(lo + o + 2) = __half2(l2, l3);
    } else {
        *reinterpret_cast<float4*>(f32out + (size_t)n * HID + c) = acc;
    }
}

// ================= WMMA fp16 2-pass GEMM, cp.async 3-stage pipeline =================
// C[M,512] = Ahi@B^T + Alo@B^T  (fp32 accum)
#define GBM 128
#define GBN 256
#define GBK 32
#define LDS_T 40                      // 32 + 8 pad fp16 elems (80B stride)
#define STAGE_ROWS 512                // Ahi 128 + Alo 128 + B 256
#define STAGE_ELEMS (STAGE_ROWS * LDS_T)
#define NSTAGES 3

__device__ __forceinline__ void cp16(__half* smem_dst, const __half* gsrc) {
    uint32_t s = (uint32_t)__cvta_generic_to_shared(smem_dst);
    asm volatile("cp.async.cg.shared.global [%0], [%1], 16;" :: "r"(s), "l"(gsrc));
}

__device__ __forceinline__ void load_stage(
    const __half* __restrict__ Ahi, const __half* __restrict__ Alo,
    const __half* __restrict__ B,
    __half* stage, int m0, int n0, int k0, int K, int tid)
{
    // 512 rows x 64B = 2048 16B chunks; 256 threads -> 8 each
    #pragma unroll
    for (int i = 0; i < 8; i++) {
        int o   = tid + i * 256;
        int row = o >> 2;
        int q   = o & 3;
        const __half* g;
        if      (row < 128) g = Ahi + (size_t)(m0 + row)       * K + k0;
        else if (row < 256) g = Alo + (size_t)(m0 + row - 128) * K + k0;
        else                g = B   + (size_t)(n0 + row - 256) * K + k0;
        cp16(stage + row * LDS_T + q * 8, g + q * 8);
    }
}

__global__ __launch_bounds__(256, 1) void gemm_wmma(
    const __half* __restrict__ Ahi, const __half* __restrict__ Alo,
    const __half* __restrict__ B,
    float* __restrict__ C, int K)
{
    extern __shared__ __half sm[];
    const int tid = threadIdx.x;
    const int wid = tid >> 5;
    const int warp_m = wid >> 2;
    const int warp_n = wid & 3;
    const int m0 = blockIdx.x * GBM;
    const int n0 = blockIdx.y * GBN;

    wmma::fragment<wmma::accumulator, 16, 16, 16, float> c[4][4];
    #pragma unroll
    for (int i = 0; i < 4; i++)
        #pragma unroll
        for (int j = 0; j < 4; j++) wmma::fill_fragment(c[i][j], 0.0f);

    const int nchunks = K / GBK;   // >= 4 always (K=128 or 512)

    load_stage(Ahi, Alo, B, sm, m0, n0, 0, K, tid);
    asm volatile("cp.async.commit_group;");
    load_stage(Ahi, Alo, B, sm + STAGE_ELEMS, m0, n0, GBK, K, tid);
    asm volatile("cp.async.commit_group;");

    for (int ch = 0; ch < nchunks; ch++) {
        if (ch + 2 < nchunks) {
            load_stage(Ahi, Alo, B, sm + ((ch + 2) % NSTAGES) * STAGE_ELEMS,
                       m0, n0, (ch + 2) * GBK, K, tid);
            asm volatile("cp.async.commit_group;");
            asm volatile("cp.async.wait_group 2;");
        } else if (ch + 1 < nchunks) {
            asm volatile("cp.async.wait_group 1;");
        } else {
            asm volatile("cp.async.wait_group 0;");
        }
        __syncthreads();

        __half* st = sm + (ch % NSTAGES) * STAGE_ELEMS;
        __half* sAhi = st;
        __half* sAlo = st + 128 * LDS_T;
        __half* sB   = st + 256 * LDS_T;

        #pragma unroll
        for (int ks = 0; ks < GBK; ks += 16) {
            wmma::fragment<wmma::matrix_b, 16, 16, 16, __half, wmma::col_major> bf[4];
            wmma::fragment<wmma::matrix_a, 16, 16, 16, __half, wmma::row_major> ah[4], al[4];
            #pragma unroll
            for (int j = 0; j < 4; j++) {
                int nn = warp_n * 64 + j * 16;
                wmma::load_matrix_sync(bf[j], sB + nn * LDS_T + ks, LDS_T);
            }
            #pragma unroll
            for (int i = 0; i < 4; i++) {
                int mm = warp_m * 64 + i * 16;
                wmma::load_matrix_sync(ah[i], sAhi + mm * LDS_T + ks, LDS_T);
                wmma::load_matrix_sync(al[i], sAlo + mm * LDS_T + ks, LDS_T);
            }
            #pragma unroll
            for (int i = 0; i < 4; i++)
                #pragma unroll
                for (int j = 0; j < 4; j++)
                    wmma::mma_sync(c[i][j], ah[i], bf[j], c[i][j]);
            #pragma unroll
            for (int i = 0; i < 4; i++)
                #pragma unroll
                for (int j = 0; j < 4; j++)
                    wmma::mma_sync(c[i][j], al[i], bf[j], c[i][j]);
        }
        __syncthreads();
    }

    #pragma unroll
    for (int i = 0; i < 4; i++) {
        int row = m0 + warp_m * 64 + i * 16;
        #pragma unroll
        for (int j = 0; j < 4; j++) {
            int col = n0 + warp_n * 64 + j * 16;
            wmma::store_matrix_sync(C + (size_t)row * HID + col, c[i][j], HID,
                                    wmma::mem_row_major);
        }
    }
}

// ---------------- pooling ----------------
__global__ void count_kernel(const int* __restrict__ gid, float* __restrict__ cnt) {
    __shared__ int s[N_GRAPHS];
    if (threadIdx.x < N_GRAPHS) s[threadIdx.x] = 0;
    __syncthreads();
    for (int i = threadIdx.x; i < N_NODES; i += blockDim.x)
        atomicAdd(&s[gid[i]], 1);
    __syncthreads();
    if (threadIdx.x < N_GRAPHS) cnt[threadIdx.x] = (float)s[threadIdx.x];
}

#define POOL_CHUNK 160
__global__ void pool_kernel(const float* __restrict__ h, const int* __restrict__ gid,
                            float* __restrict__ pool) {
    __shared__ int sg[POOL_CHUNK];
    int n0 = blockIdx.x * POOL_CHUNK;
    int n1 = min(n0 + POOL_CHUNK, N_NODES);
    for (int i = threadIdx.x; i < n1 - n0; i += blockDim.x) sg[i] = gid[n0 + i];
    __syncthreads();

    int c = threadIdx.x * 4;
    float4 acc = make_float4(0.f, 0.f, 0.f, 0.f);
    int cur = sg[0];
    for (int n = n0; n < n1; n++) {
        int g = sg[n - n0];
        if (g != cur) {
            float* p = pool + cur * HID + c;
            atomicAdd(p + 0, acc.x); atomicAdd(p + 1, acc.y);
            atomicAdd(p + 2, acc.z); atomicAdd(p + 3, acc.w);
            acc = make_float4(0.f, 0.f, 0.f, 0.f);
            cur = g;
        }
        float4 v = *reinterpret_cast<const float4*>(h + n * HID + c);
        acc.x += v.x; acc.y += v.y; acc.z += v.z; acc.w += v.w;
    }
    float* p = pool + cur * HID + c;
    atomicAdd(p + 0, acc.x); atomicAdd(p + 1, acc.y);
    atomicAdd(p + 2, acc.z); atomicAdd(p + 3, acc.w);
}

__global__ void div_kernel(float* __restrict__ pool, const float* __restrict__ cnt) {
    int i = blockIdx.x * blockDim.x + threadIdx.x;
    if (i < N_GRAPHS * HID) {
        float inv = 1.0f / fmaxf(cnt[i / HID], 1.0f);
        pool[i] *= inv;
    }
}

// ---------------- MLP head ----------------
__global__ void dense512(const float* __restrict__ in, const float* __restrict__ W,
                         const float* __restrict__ b, float* __restrict__ out) {
    __shared__ float sh[HID];
    int g = blockIdx.x;
    for (int i = threadIdx.x; i < HID; i += blockDim.x) sh[i] = in[g * HID + i];
    __syncthreads();
    int n = blockIdx.y * 256 + threadIdx.x;
    float acc = b[n];
    #pragma unroll 8
    for (int k = 0; k < HID; k++)
        acc = fmaf(sh[k], W[k * HID + n], acc);
    out[g * HID + n] = fmaxf(acc, 0.0f);
}

__global__ void dense_out(const float* __restrict__ in, const float* __restrict__ W,
                          const float* __restrict__ b, float* __restrict__ out) {
    int g = blockIdx.x;
    int n = threadIdx.x;
    float acc = b[n];
    for (int k = 0; k < HID; k++)
        acc = fmaf(in[g * HID + k], W[k * N_CLASSES + n], acc);
    out[g * N_CLASSES + n] = acc;
}

// ---------------- launch ----------------
extern "C" void kernel_launch(void* const* d_in, const int* in_sizes, int n_in,
                              void* d_out, int out_size) {
    const float* x    = (const float*)d_in[0];
    const int*   src  = (const int*)  d_in[1];
    const int*   dst  = (const int*)  d_in[2];
    const int*   gid  = (const int*)  d_in[3];
    const float* W1   = (const float*)d_in[4];
    const float* b1   = (const float*)d_in[5];
    const float* W2   = (const float*)d_in[6];
    const float* b2   = (const float*)d_in[7];
    const float* W3   = (const float*)d_in[8];
    const float* b3   = (const float*)d_in[9];
    const float* Wc1  = (const float*)d_in[10];
    const float* bc1  = (const float*)d_in[11];
    const float* Wc2  = (const float*)d_in[12];
    const float* bc2  = (const float*)d_in[13];
    const float* Wc3  = (const float*)d_in[14];
    const float* bc3  = (const float*)d_in[15];
    float* out = (float*)d_out;

    float *bufA, *bufB, *doutv, *dinv, *pool, *cnt, *m1, *m2;
    int *cin_, *cout_, *rowoff, *cursor, *csrc;
    __half *Ahi, *Alo, *Wt;
    cudaGetSymbolAddress((void**)&bufA,   g_bufA);
    cudaGetSymbolAddress((void**)&bufB,   g_bufB);
    cudaGetSymbolAddress((void**)&doutv,  g_dout);
    cudaGetSymbolAddress((void**)&dinv,   g_din);
    cudaGetSymbolAddress((void**)&pool,   g_pool);
    cudaGetSymbolAddress((void**)&cnt,    g_cnt);
    cudaGetSymbolAddress((void**)&m1,     g_mlp1);
    cudaGetSymbolAddress((void**)&m2,     g_mlp2);
    cudaGetSymbolAddress((void**)&cin_,   g_cin);
    cudaGetSymbolAddress((void**)&cout_,  g_cout);
    cudaGetSymbolAddress((void**)&rowoff, g_rowoff);
    cudaGetSymbolAddress((void**)&cursor, g_cursor);
    cudaGetSymbolAddress((void**)&csrc,   g_csrc);
    cudaGetSymbolAddress((void**)&Ahi,    g_Ahi);
    cudaGetSymbolAddress((void**)&Alo,    g_Alo);
    cudaGetSymbolAddress((void**)&Wt,     g_Wt);

    const int smem_gemm = NSTAGES * STAGE_ELEMS * (int)sizeof(__half);  // 122880
    cudaFuncSetAttribute(gemm_wmma, cudaFuncAttributeMaxDynamicSharedMemorySize, smem_gemm);

    const int nb_nodes = (N_NODES + 255) / 256;
    const int nb_edges = (N_EDGES + 255) / 256;
    dim3 gemm_grid(MROWS / GBM, HID / GBN);   // (157, 2)

    // ---- CSR build + degree normalizers ----
    zero_i2<<<nb_nodes, 256>>>(cin_, cout_, N_NODES);
    deg_kernel<<<nb_edges, 256>>>(src, dst, cout_, cin_);
    scan_kernel<<<1, 1024>>>(cin_, cout_, rowoff, cursor, dinv, doutv);
    bin_kernel<<<nb_edges, 256>>>(src, dst, cursor, csrc);

    // ---- layer 1 ----
    {
        wsplit<<<(IN_DIM * HID + 255) / 256, 256>>>(W1, Wt, IN_DIM, HID);
        int t4 = N_NODES * IN_DIM / 4;
        split_scaled<<<(t4 + 255) / 256, 256>>>(x, doutv, Ahi, Alo, t4, IN_DIM);
        gemm_wmma<<<gemm_grid, 256, smem_gemm>>>(Ahi, Alo, Wt, bufA, IN_DIM);
        gather_fin<<<N_NODES, 128>>>(bufA, csrc, rowoff, dinv, doutv, b1,
                                     Ahi, Alo, nullptr, 0);
    }
    // ---- layer 2 ----
    {
        wsplit<<<(HID * HID + 255) / 256, 256>>>(W2, Wt, HID, HID);
        gemm_wmma<<<gemm_grid, 256, smem_gemm>>>(Ahi, Alo, Wt, bufA, HID);
        gather_fin<<<N_NODES, 128>>>(bufA, csrc, rowoff, dinv, doutv, b2,
                                     Ahi, Alo, nullptr, 0);
    }
    // ---- layer 3 ----
    {
        wsplit<<<(HID * HID + 255) / 256, 256>>>(W3, Wt, HID, HID);
        gemm_wmma<<<gemm_grid, 256, smem_gemm>>>(Ahi, Alo, Wt, bufA, HID);
        gather_fin<<<N_NODES, 128>>>(bufA, csrc, rowoff, dinv, doutv, b3,
                                     nullptr, nullptr, bufB, 1);
    }

    // ---- mean pooling ----
    zero_f<<<(N_GRAPHS * HID + 255) / 256, 256>>>(pool, N_GRAPHS * HID);
    count_kernel<<<1, 256>>>(gid, cnt);
    pool_kernel<<<(N_NODES + POOL_CHUNK - 1) / POOL_CHUNK, 128>>>(bufB, gid, pool);
    div_kernel<<<(N_GRAPHS * HID + 255) / 256, 256>>>(pool, cnt);

    // ---- MLP head ----
    dense512<<<dim3(N_GRAPHS, 2), 256>>>(pool, Wc1, bc1, m1);
    dense512<<<dim3(N_GRAPHS, 2), 256>>>(m1, Wc2, bc2, m2);
    dense_out<<<N_GRAPHS, 16>>>(m2, Wc3, bc3, out);
}